// round 10
// baseline (speedup 1.0000x reference)
#include <cuda_runtime.h>
#include <cuda_bf16.h>
#include <mma.h>
#include <cstdint>

using namespace nvcuda;

#define DI __device__ __forceinline__

static constexpr int NT = 512;   // 16 warps: two K-split groups of 8
static constexpr int SB = 136;   // bf16 tile stride (elems)
static constexpr int SP = 72;    // P (alphas) bf16 stride
static constexpr int SF = 132;   // fp32 proj/epilogue temp stride
static constexpr int SS = 68;    // fp32 scores temp stride

// ---- smem byte offsets ----
static constexpr int XHI = 0;         // x hi [64][SB]   17408 B
static constexpr int XLO = 17408;
static constexpr int WA  = 34816;     // staged W hi [128][SB]  34816 B
static constexpr int WB  = 69632;     // staged W lo
static constexpr int THI = 104448;    // T hi [64][SB]; later P [64][SP]
static constexpr int TLO = 121856;
static constexpr int VHI = 139264;    // v hi [64][SB]
static constexpr int VLO = 156672;
static constexpr int TMP = 174080;    // fp32 [64][SF] (33792 B), scores alias stride SS
static constexpr int SMEM_BYTES = TMP + 64 * SF * 4;   // 207872 -> 1 CTA/SM

// prepped matrices, bf16 hi/lo: slot0 = G^T (G = Wq·Wk^T), slot1 = Wv^T, slot2 = Wr^T
__device__ __align__(16) __nv_bfloat16 g_Whi[3][128 * 128];
__device__ __align__(16) __nv_bfloat16 g_Wlo[3][128 * 128];

DI unsigned pack2(__nv_bfloat16 a, __nv_bfloat16 b) {
    return (unsigned)__bfloat16_as_ushort(a) | ((unsigned)__bfloat16_as_ushort(b) << 16);
}
DI void split2(float v0, float v1, unsigned& h, unsigned& l) {
    __nv_bfloat16 h0 = __float2bfloat16_rn(v0), h1 = __float2bfloat16_rn(v1);
    __nv_bfloat16 l0 = __float2bfloat16_rn(v0 - __bfloat162float(h0));
    __nv_bfloat16 l1 = __float2bfloat16_rn(v1 - __bfloat162float(h1));
    h = pack2(h0, h1); l = pack2(l0, l1);
}
DI void cpa16(uint32_t dst, const void* src) {
    asm volatile("cp.async.cg.shared.global [%0], [%1], 16;" :: "r"(dst), "l"(src));
}
#define CPA_COMMIT() asm volatile("cp.async.commit_group;" ::: "memory")
#define CPA_WAIT()   asm volatile("cp.async.wait_group 0;" ::: "memory")

// ------------------------------------------------ prep kernels (once/replay)
// G^T[j][d] = sum_e Wq[d,e] * Wk[j,e]   (vectorized: 32 float4 pairs)
__global__ void prep_g(const float* __restrict__ Wq, const float* __restrict__ Wk) {
    int idx = blockIdx.x * 128 + threadIdx.x;   // 16384 over 128 blocks
    int j = idx >> 7, d = idx & 127;
    const float4* wq = (const float4*)(Wq + d * 128);
    const float4* wk = (const float4*)(Wk + j * 128);
    float s = 0.f;
#pragma unroll
    for (int e = 0; e < 32; e++) {
        float4 a = wq[e], c = wk[e];
        s = fmaf(a.x, c.x, fmaf(a.y, c.y, fmaf(a.z, c.z, fmaf(a.w, c.w, s))));
    }
    __nv_bfloat16 hi = __float2bfloat16_rn(s);
    g_Whi[0][j * 128 + d] = hi;
    g_Wlo[0][j * 128 + d] = __float2bfloat16_rn(s - __bfloat162float(hi));
}
__global__ void prep_w(const float* __restrict__ Wv, const float* __restrict__ Wr) {
    int i = blockIdx.x * 256 + threadIdx.x;     // 32768
    int p = i >> 14, rem = i & 16383;
    int d = rem >> 7, e = rem & 127;
    float w = (p ? Wr : Wv)[rem];
    __nv_bfloat16 hi = __float2bfloat16_rn(w);
    g_Whi[p + 1][e * 128 + d] = hi;
    g_Wlo[p + 1][e * 128 + d] = __float2bfloat16_rn(w - __bfloat162float(hi));
}

// ---------------------------------------------------------------- main kernel
using FA  = wmma::fragment<wmma::matrix_a, 16, 16, 16, __nv_bfloat16, wmma::row_major>;
using FBc = wmma::fragment<wmma::matrix_b, 16, 16, 16, __nv_bfloat16, wmma::col_major>;
using FBr = wmma::fragment<wmma::matrix_b, 16, 16, 16, __nv_bfloat16, wmma::row_major>;
using FC  = wmma::fragment<wmma::accumulator, 16, 16, 16, float>;

__global__ __launch_bounds__(NT, 1)
void autoint_hmma(const float* __restrict__ x, float* __restrict__ out) {
    extern __shared__ __align__(16) char sm[];
    const uint32_t smb = (uint32_t)__cvta_generic_to_shared(sm);
    const int b   = blockIdx.x;
    const int tid = threadIdx.x;
    const int wid = tid >> 5;
    const int grp = wid >> 3;          // K-split group: 0 -> low half, 1 -> high half
    const int w8  = wid & 7;           // warp index within group

    // 2x2 tile geometry per warp (identical to round 9), per K-half
    const int m0 = 32 * (w8 >> 2);
    const int n0 = 32 * (w8 & 3);

    const __nv_bfloat16* xhi = (const __nv_bfloat16*)(sm + XHI);
    const __nv_bfloat16* xlo = (const __nv_bfloat16*)(sm + XLO);
    const __nv_bfloat16* wa  = (const __nv_bfloat16*)(sm + WA);
    const __nv_bfloat16* wb  = (const __nv_bfloat16*)(sm + WB);
    float* tmpp = (float*)(sm + TMP);

    auto stageW = [&](int dst, const __nv_bfloat16* g) {
        const char* gs = (const char*)g;
#pragma unroll
        for (int i = 0; i < 4; i++) {
            int idx = tid + i * NT;                  // 2048 x 16B chunks
            cpa16(smb + dst + (idx >> 4) * (SB * 2) + (idx & 15) * 16, gs + idx * 16);
        }
        CPA_COMMIT();
    };
    auto convert = [&](int dh, int dl) {             // fp32 TMP(SF) -> bf16 hi/lo(SB)
        const int r = tid >> 3, c0v = (tid & 7) * 16;
#pragma unroll
        for (int jj = 0; jj < 4; jj++) {
            float4 f = *(const float4*)(tmpp + r * SF + c0v + jj * 4);
            unsigned h0, l0, h1, l1;
            split2(f.x, f.y, h0, l0);
            split2(f.z, f.w, h1, l1);
            *(uint2*)(sm + dh + (r * SB + c0v + jj * 4) * 2) = make_uint2(h0, h1);
            *(uint2*)(sm + dl + (r * SB + c0v + jj * 4) * 2) = make_uint2(l0, l1);
        }
    };
    // merge group-1 partials into group-0 accumulators through TMP (stride argument)
    // g1 stores; sync; g0 loads+adds. Caller provides store/load positions.

    // ---- phase 0: stage G (hi+lo, async) while loading + splitting x ----
    stageW(WA, g_Whi[0]);
    stageW(WB, g_Wlo[0]);
    {
        const float4* gx = (const float4*)(x + (size_t)b * 8192);
#pragma unroll
        for (int i = 0; i < 4; i++) {
            int idx = tid + i * NT;
            int row = idx >> 5, c = (idx & 31) * 4;
            float4 f = gx[idx];
            unsigned h0, l0, h1, l1;
            split2(f.x, f.y, h0, l0);
            split2(f.z, f.w, h1, l1);
            *(uint2*)(sm + XHI + (row * SB + c) * 2) = make_uint2(h0, h1);
            *(uint2*)(sm + XLO + (row * SB + c) * 2) = make_uint2(l0, l1);
        }
    }
    CPA_WAIT();
    __syncthreads();

    // ---- phases 1,2: T = X@G then V = X@Wv (3-term, K split across groups) ----
    const int DH[2] = {THI, VHI};
    const int DL[2] = {TLO, VLO};
#pragma unroll 1
    for (int p = 0; p < 2; p++) {
        FC acc[2][2];
#pragma unroll
        for (int i = 0; i < 2; i++)
#pragma unroll
            for (int j = 0; j < 2; j++) wmma::fill_fragment(acc[i][j], 0.0f);

        const int kb = grp * 64;
#pragma unroll
        for (int kk = 0; kk < 64; kk += 16) {
            const int k = kb + kk;
            FA ah[2], al[2];
            FBc bh[2], bl[2];
#pragma unroll
            for (int i = 0; i < 2; i++) {
                wmma::load_matrix_sync(ah[i], xhi + (m0 + 16 * i) * SB + k, SB);
                wmma::load_matrix_sync(al[i], xlo + (m0 + 16 * i) * SB + k, SB);
            }
#pragma unroll
            for (int j = 0; j < 2; j++) {
                wmma::load_matrix_sync(bh[j], wa + (n0 + 16 * j) * SB + k, SB);
                wmma::load_matrix_sync(bl[j], wb + (n0 + 16 * j) * SB + k, SB);
            }
#pragma unroll
            for (int i = 0; i < 2; i++)
#pragma unroll
                for (int j = 0; j < 2; j++) {
                    wmma::mma_sync(acc[i][j], ah[i], bh[j], acc[i][j]);
                    wmma::mma_sync(acc[i][j], ah[i], bl[j], acc[i][j]);
                    wmma::mma_sync(acc[i][j], al[i], bh[j], acc[i][j]);
                }
        }

        // merge K-halves: g1 stores, g0 adds
        if (grp == 1) {
#pragma unroll
            for (int i = 0; i < 2; i++)
#pragma unroll
                for (int j = 0; j < 2; j++)
                    wmma::store_matrix_sync(tmpp + (m0 + 16 * i) * SF + (n0 + 16 * j),
                                            acc[i][j], SF, wmma::mem_row_major);
        }
        __syncthreads();
        if (grp == 0) {
#pragma unroll
            for (int i = 0; i < 2; i++)
#pragma unroll
                for (int j = 0; j < 2; j++) {
                    FC t;
                    wmma::load_matrix_sync(t, tmpp + (m0 + 16 * i) * SF + (n0 + 16 * j),
                                           SF, wmma::mem_row_major);
#pragma unroll
                    for (int e = 0; e < t.num_elements; e++) acc[i][j].x[e] += t.x[e];
                    wmma::store_matrix_sync(tmpp + (m0 + 16 * i) * SF + (n0 + 16 * j),
                                            acc[i][j], SF, wmma::mem_row_major);
                }
        }
        __syncthreads();

        stageW(WA, g_Whi[p + 1]);            // async next matrix during convert
        stageW(WB, g_Wlo[p + 1]);
        convert(DH[p], DL[p]);
        CPA_WAIT();
        __syncthreads();
    }
    // WA/WB now hold Wr hi/lo

    // ---- phase 3: scores = T @ X^T (64x64, K=128 split) ----
    {
        const int sm0 = 16 * (w8 & 3);
        const int sn0 = 32 * (w8 >> 2);
        const int kb  = grp * 64;
        const __nv_bfloat16* thi = (const __nv_bfloat16*)(sm + THI);
        const __nv_bfloat16* tlo = (const __nv_bfloat16*)(sm + TLO);
        FC acc[2];
        wmma::fill_fragment(acc[0], 0.0f);
        wmma::fill_fragment(acc[1], 0.0f);
#pragma unroll
        for (int kk = 0; kk < 64; kk += 16) {
            const int k = kb + kk;
            FA th, tl;
            FBc xh[2], xl[2];
            wmma::load_matrix_sync(th, thi + sm0 * SB + k, SB);
            wmma::load_matrix_sync(tl, tlo + sm0 * SB + k, SB);
#pragma unroll
            for (int j = 0; j < 2; j++) {
                wmma::load_matrix_sync(xh[j], xhi + (sn0 + 16 * j) * SB + k, SB);
                wmma::load_matrix_sync(xl[j], xlo + (sn0 + 16 * j) * SB + k, SB);
            }
#pragma unroll
            for (int j = 0; j < 2; j++) {
                wmma::mma_sync(acc[j], th, xh[j], acc[j]);
                wmma::mma_sync(acc[j], th, xl[j], acc[j]);
                wmma::mma_sync(acc[j], tl, xh[j], acc[j]);
            }
        }
        float* tmps = (float*)(sm + TMP);    // stride SS
        if (grp == 1) {
#pragma unroll
            for (int j = 0; j < 2; j++)
                wmma::store_matrix_sync(tmps + sm0 * SS + sn0 + 16 * j, acc[j], SS,
                                        wmma::mem_row_major);
        }
        __syncthreads();
        if (grp == 0) {
#pragma unroll
            for (int j = 0; j < 2; j++) {
                FC t;
                wmma::load_matrix_sync(t, tmps + sm0 * SS + sn0 + 16 * j, SS,
                                       wmma::mem_row_major);
#pragma unroll
                for (int e = 0; e < t.num_elements; e++) acc[j].x[e] += t.x[e];
                wmma::store_matrix_sync(tmps + sm0 * SS + sn0 + 16 * j, acc[j], SS,
                                        wmma::mem_row_major);
            }
        }
        __syncthreads();
    }

    // ---- phase 4: softmax rows -> P hi/lo (overwrites T, stride SP) ----
    {
        const float* tmps = (const float*)(sm + TMP);
        const int r = tid >> 3, q0 = (tid & 7) * 8;
        float s[8];
#pragma unroll
        for (int j = 0; j < 8; j += 4) {
            float4 f = *(const float4*)(tmps + r * SS + q0 + j);
            s[j] = f.x; s[j + 1] = f.y; s[j + 2] = f.z; s[j + 3] = f.w;
        }
        float mx = s[0];
#pragma unroll
        for (int j = 1; j < 8; j++) mx = fmaxf(mx, s[j]);
        mx = fmaxf(mx, __shfl_xor_sync(0xffffffffu, mx, 1));
        mx = fmaxf(mx, __shfl_xor_sync(0xffffffffu, mx, 2));
        mx = fmaxf(mx, __shfl_xor_sync(0xffffffffu, mx, 4));
        float sum = 0.f;
#pragma unroll
        for (int j = 0; j < 8; j++) { s[j] = __expf(s[j] - mx); sum += s[j]; }
        sum += __shfl_xor_sync(0xffffffffu, sum, 1);
        sum += __shfl_xor_sync(0xffffffffu, sum, 2);
        sum += __shfl_xor_sync(0xffffffffu, sum, 4);
        const float inv = 1.0f / sum;
#pragma unroll
        for (int j = 0; j < 8; j += 2) {
            unsigned h, l;
            split2(s[j] * inv, s[j + 1] * inv, h, l);
            *(unsigned*)(sm + THI + (r * SP + q0 + j) * 2) = h;
            *(unsigned*)(sm + TLO + (r * SP + q0 + j) * 2) = l;
        }
    }
    __syncthreads();

    // ---- phase 5: epilogue acc = P@V + X@Wr (both K-split), relu, store ----
    {
        const __nv_bfloat16* phi = (const __nv_bfloat16*)(sm + THI);
        const __nv_bfloat16* plo = (const __nv_bfloat16*)(sm + TLO);
        const __nv_bfloat16* vhi = (const __nv_bfloat16*)(sm + VHI);
        const __nv_bfloat16* vlo = (const __nv_bfloat16*)(sm + VLO);
        FC acc[2][2];
#pragma unroll
        for (int i = 0; i < 2; i++)
#pragma unroll
            for (int j = 0; j < 2; j++) wmma::fill_fragment(acc[i][j], 0.0f);

        // P @ V : K=64, this group's half = 32
        const int kbp = grp * 32;
#pragma unroll
        for (int kk = 0; kk < 32; kk += 16) {
            const int k = kbp + kk;
            FA ph[2], pl[2];
            FBr vh[2], vl[2];
#pragma unroll
            for (int i = 0; i < 2; i++) {
                wmma::load_matrix_sync(ph[i], phi + (m0 + 16 * i) * SP + k, SP);
                wmma::load_matrix_sync(pl[i], plo + (m0 + 16 * i) * SP + k, SP);
            }
#pragma unroll
            for (int j = 0; j < 2; j++) {
                wmma::load_matrix_sync(vh[j], vhi + k * SB + n0 + 16 * j, SB);
                wmma::load_matrix_sync(vl[j], vlo + k * SB + n0 + 16 * j, SB);
            }
#pragma unroll
            for (int i = 0; i < 2; i++)
#pragma unroll
                for (int j = 0; j < 2; j++) {
                    wmma::mma_sync(acc[i][j], ph[i], vh[j], acc[i][j]);
                    wmma::mma_sync(acc[i][j], ph[i], vl[j], acc[i][j]);
                    wmma::mma_sync(acc[i][j], pl[i], vh[j], acc[i][j]);
                }
        }

        // += X @ Wr : K=128, this group's half = 64
        const int kbr = grp * 64;
#pragma unroll
        for (int kk = 0; kk < 64; kk += 16) {
            const int k = kbr + kk;
            FA ah[2], al[2];
            FBc wh[2], wl[2];
#pragma unroll
            for (int i = 0; i < 2; i++) {
                wmma::load_matrix_sync(ah[i], xhi + (m0 + 16 * i) * SB + k, SB);
                wmma::load_matrix_sync(al[i], xlo + (m0 + 16 * i) * SB + k, SB);
            }
#pragma unroll
            for (int j = 0; j < 2; j++) {
                wmma::load_matrix_sync(wh[j], wa + (n0 + 16 * j) * SB + k, SB);
                wmma::load_matrix_sync(wl[j], wb + (n0 + 16 * j) * SB + k, SB);
            }
#pragma unroll
            for (int i = 0; i < 2; i++)
#pragma unroll
                for (int j = 0; j < 2; j++) {
                    wmma::mma_sync(acc[i][j], ah[i], wh[j], acc[i][j]);
                    wmma::mma_sync(acc[i][j], ah[i], wl[j], acc[i][j]);
                    wmma::mma_sync(acc[i][j], al[i], wh[j], acc[i][j]);
                }
        }

        // merge + relu + store
        if (grp == 1) {
#pragma unroll
            for (int i = 0; i < 2; i++)
#pragma unroll
                for (int j = 0; j < 2; j++)
                    wmma::store_matrix_sync(tmpp + (m0 + 16 * i) * SF + (n0 + 16 * j),
                                            acc[i][j], SF, wmma::mem_row_major);
        }
        __syncthreads();
        if (grp == 0) {
            float* outp = out + (size_t)b * 8192;
#pragma unroll
            for (int i = 0; i < 2; i++)
#pragma unroll
                for (int j = 0; j < 2; j++) {
                    FC t;
                    wmma::load_matrix_sync(t, tmpp + (m0 + 16 * i) * SF + (n0 + 16 * j),
                                           SF, wmma::mem_row_major);
#pragma unroll
                    for (int e = 0; e < t.num_elements; e++)
                        acc[i][j].x[e] = fmaxf(acc[i][j].x[e] + t.x[e], 0.0f);
                    wmma::store_matrix_sync(outp + (m0 + 16 * i) * 128 + (n0 + 16 * j),
                                            acc[i][j], 128, wmma::mem_row_major);
                }
        }
    }
}

extern "C" void kernel_launch(void* const* d_in, const int* in_sizes, int n_in,
                              void* d_out, int out_size) {
    const float* x  = (const float*)d_in[0];
    const float* Wq = (const float*)d_in[1];
    const float* Wk = (const float*)d_in[2];
    const float* Wv = (const float*)d_in[3];
    const float* Wr = (const float*)d_in[4];
    float* out = (float*)d_out;

    prep_g<<<128, 128>>>(Wq, Wk);
    prep_w<<<128, 256>>>(Wv, Wr);
    cudaFuncSetAttribute(autoint_hmma,
                         cudaFuncAttributeMaxDynamicSharedMemorySize, SMEM_BYTES);
    autoint_hmma<<<8192, NT, SMEM_BYTES>>>(x, out);
}

// round 11
// speedup vs baseline: 1.0580x; 1.0580x over previous
#include <cuda_runtime.h>
#include <cuda_bf16.h>
#include <mma.h>
#include <cstdint>

using namespace nvcuda;

#define DI __device__ __forceinline__

static constexpr int NT = 256;
static constexpr int SB = 136;   // bf16 tile stride (elems)
static constexpr int SP = 72;    // P (alphas) bf16 stride
static constexpr int SF = 132;   // fp32 temp stride
static constexpr int SS = 68;    // fp32 scores stride

// ---- smem byte offsets ----
static constexpr int XHI = 0;          // x hi [64][SB]  17408 B
static constexpr int XLO = 17408;
static constexpr int WA  = 34816;      // staged W hi [128][SB] 34816 B
static constexpr int WB  = 69632;      // staged W lo
static constexpr int THI = 104448;     // T hi; later P (stride SP)
static constexpr int TLO = 121856;
static constexpr int VHI = 139264;     // V hi
static constexpr int VLO = 156672;
static constexpr int TMP = 174080;     // fp32 [64][SF] = 33792 B
static constexpr int SC  = 207872;     // fp32 scores [64][SS] = 17408 B
static constexpr int SMEM_BYTES = SC + 64 * SS * 4;   // 225280 B

// prepped: slot0 = G^T (G = Wq·Wk^T), slot1 = Wv^T, slot2 = Wr^T (bf16 hi/lo)
__device__ __align__(16) __nv_bfloat16 g_Whi[3][128 * 128];
__device__ __align__(16) __nv_bfloat16 g_Wlo[3][128 * 128];

DI unsigned pack2(__nv_bfloat16 a, __nv_bfloat16 b) {
    return (unsigned)__bfloat16_as_ushort(a) | ((unsigned)__bfloat16_as_ushort(b) << 16);
}
DI void split2(float v0, float v1, unsigned& h, unsigned& l) {
    __nv_bfloat16 h0 = __float2bfloat16_rn(v0), h1 = __float2bfloat16_rn(v1);
    __nv_bfloat16 l0 = __float2bfloat16_rn(v0 - __bfloat162float(h0));
    __nv_bfloat16 l1 = __float2bfloat16_rn(v1 - __bfloat162float(h1));
    h = pack2(h0, h1); l = pack2(l0, l1);
}
DI void cpa16(uint32_t dst, const void* src) {
    asm volatile("cp.async.cg.shared.global [%0], [%1], 16;" :: "r"(dst), "l"(src));
}
#define CPA_COMMIT() asm volatile("cp.async.commit_group;" ::: "memory")
#define CPA_WAIT()   asm volatile("cp.async.wait_group 0;" ::: "memory")
#define BAR(id)      asm volatile("bar.sync %0, 128;" :: "r"(id) : "memory")

// ------------------------------------------------ merged prep kernel
__global__ void prep_all(const float* __restrict__ Wq, const float* __restrict__ Wk,
                         const float* __restrict__ Wv, const float* __restrict__ Wr) {
    const int blk = blockIdx.x;
    if (blk < 128) {
        // G^T[j][d] = dot(Wq[d,:], Wk[j,:]); 2 threads per output
        int gid = blk * 256 + threadIdx.x;         // 32768
        int o = gid >> 1, half = gid & 1;
        int j = o >> 7, d = o & 127;
        const float4* wq = (const float4*)(Wq + d * 128) + half * 16;
        const float4* wk = (const float4*)(Wk + j * 128) + half * 16;
        float s = 0.f;
#pragma unroll
        for (int e = 0; e < 16; e++) {
            float4 a = wq[e], c = wk[e];
            s = fmaf(a.x, c.x, fmaf(a.y, c.y, fmaf(a.z, c.z, fmaf(a.w, c.w, s))));
        }
        s += __shfl_xor_sync(0xffffffffu, s, 1);
        if (!half) {
            __nv_bfloat16 hi = __float2bfloat16_rn(s);
            g_Whi[0][j * 128 + d] = hi;
            g_Wlo[0][j * 128 + d] = __float2bfloat16_rn(s - __bfloat162float(hi));
        }
    } else {
        int i = (blk - 128) * 256 + threadIdx.x;   // 32768
        int p = i >> 14, rem = i & 16383;
        int d = rem >> 7, e = rem & 127;
        float w = (p ? Wr : Wv)[rem];
        __nv_bfloat16 hi = __float2bfloat16_rn(w);
        g_Whi[p + 1][e * 128 + d] = hi;
        g_Wlo[p + 1][e * 128 + d] = __float2bfloat16_rn(w - __bfloat162float(hi));
    }
}

// ---------------------------------------------------------------- main kernel
using FA  = wmma::fragment<wmma::matrix_a, 16, 16, 16, __nv_bfloat16, wmma::row_major>;
using FBc = wmma::fragment<wmma::matrix_b, 16, 16, 16, __nv_bfloat16, wmma::col_major>;
using FBr = wmma::fragment<wmma::matrix_b, 16, 16, 16, __nv_bfloat16, wmma::row_major>;
using FC  = wmma::fragment<wmma::accumulator, 16, 16, 16, float>;

__global__ __launch_bounds__(NT, 1)
void autoint_hmma(const float* __restrict__ x, float* __restrict__ out) {
    extern __shared__ __align__(16) char sm[];
    const uint32_t smb = (uint32_t)__cvta_generic_to_shared(sm);
    const int b    = blockIdx.x;
    const int tid  = threadIdx.x;
    const int wid  = tid >> 5;
    const int grp  = wid >> 2;        // 0: warps 0-3, 1: warps 4-7
    const int w4   = wid & 3;
    const int ltid = tid & 127;       // thread id within group

    // phase-1 (all-warp) 2x2 tile geometry (round-9 proven)
    const int m0 = 32 * (wid >> 2);
    const int n0 = 32 * (wid & 3);
    // fat 2m x 4n tile geometry (4-warp GEMMs over [64 x 128])
    const int fm0 = 32 * (w4 >> 1);
    const int fn0 = 64 * (w4 & 1);

    const __nv_bfloat16* xhi = (const __nv_bfloat16*)(sm + XHI);
    const __nv_bfloat16* xlo = (const __nv_bfloat16*)(sm + XLO);
    const __nv_bfloat16* wa  = (const __nv_bfloat16*)(sm + WA);
    const __nv_bfloat16* wb  = (const __nv_bfloat16*)(sm + WB);
    float* tmpp = (float*)(sm + TMP);

    // all-thread async stage of one 128x128 bf16 matrix
    auto stageW = [&](int dst, const __nv_bfloat16* g) {
        const char* gs = (const char*)g;
#pragma unroll
        for (int i = 0; i < 8; i++) {
            int idx = tid + i * NT;
            cpa16(smb + dst + (idx >> 4) * (SB * 2) + (idx & 15) * 16, gs + idx * 16);
        }
        CPA_COMMIT();
    };
    // group-local (128-thread) async stage
    auto stageW_h = [&](int dst, const __nv_bfloat16* g) {
        const char* gs = (const char*)g;
#pragma unroll
        for (int i = 0; i < 16; i++) {
            int idx = ltid + i * 128;
            cpa16(smb + dst + (idx >> 4) * (SB * 2) + (idx & 15) * 16, gs + idx * 16);
        }
        CPA_COMMIT();
    };

    // ---- phase 0: stage G hi/lo while loading + splitting x ----
    stageW(WA, g_Whi[0]);
    stageW(WB, g_Wlo[0]);
    {
        const float4* gx = (const float4*)(x + (size_t)b * 8192);
#pragma unroll
        for (int i = 0; i < 8; i++) {
            int idx = tid + i * NT;
            int row = idx >> 5, c = (idx & 31) * 4;
            float4 f = gx[idx];
            unsigned h0, l0, h1, l1;
            split2(f.x, f.y, h0, l0);
            split2(f.z, f.w, h1, l1);
            *(uint2*)(sm + XHI + (row * SB + c) * 2) = make_uint2(h0, h1);
            *(uint2*)(sm + XLO + (row * SB + c) * 2) = make_uint2(l0, l1);
        }
    }
    CPA_WAIT();
    __syncthreads();

    // ---- phase 1: T = X@G (all 8 warps, 2x2, 3-term) ----
    {
        FC acc[2][2];
#pragma unroll
        for (int i = 0; i < 2; i++)
#pragma unroll
            for (int j = 0; j < 2; j++) wmma::fill_fragment(acc[i][j], 0.0f);
#pragma unroll
        for (int k = 0; k < 128; k += 16) {
            FA ah[2], al[2];
            FBc bh[2], bl[2];
#pragma unroll
            for (int i = 0; i < 2; i++) {
                wmma::load_matrix_sync(ah[i], xhi + (m0 + 16 * i) * SB + k, SB);
                wmma::load_matrix_sync(al[i], xlo + (m0 + 16 * i) * SB + k, SB);
            }
#pragma unroll
            for (int j = 0; j < 2; j++) {
                wmma::load_matrix_sync(bh[j], wa + (n0 + 16 * j) * SB + k, SB);
                wmma::load_matrix_sync(bl[j], wb + (n0 + 16 * j) * SB + k, SB);
            }
#pragma unroll
            for (int i = 0; i < 2; i++)
#pragma unroll
                for (int j = 0; j < 2; j++) {
                    wmma::mma_sync(acc[i][j], ah[i], bh[j], acc[i][j]);
                    wmma::mma_sync(acc[i][j], ah[i], bl[j], acc[i][j]);
                    wmma::mma_sync(acc[i][j], al[i], bh[j], acc[i][j]);
                }
        }
        __syncthreads();                 // all G reads done
#pragma unroll
        for (int i = 0; i < 2; i++)
#pragma unroll
            for (int j = 0; j < 2; j++)
                wmma::store_matrix_sync(tmpp + (m0 + 16 * i) * SF + (n0 + 16 * j),
                                        acc[i][j], SF, wmma::mem_row_major);
        __syncthreads();

        stageW(WA, g_Whi[1]);            // Wv staged during T convert
        stageW(WB, g_Wlo[1]);
        // convert T: fp32 TMP -> bf16 hi/lo
        const int r = tid >> 2, c0v = (tid & 3) * 32;
#pragma unroll
        for (int jj = 0; jj < 8; jj++) {
            float4 f = *(const float4*)(tmpp + r * SF + c0v + jj * 4);
            unsigned h0, l0, h1, l1;
            split2(f.x, f.y, h0, l0);
            split2(f.z, f.w, h1, l1);
            *(uint2*)(sm + THI + (r * SB + c0v + jj * 4) * 2) = make_uint2(h0, h1);
            *(uint2*)(sm + TLO + (r * SB + c0v + jj * 4) * 2) = make_uint2(l0, l1);
        }
        CPA_WAIT();
        __syncthreads();
    }

    // ---- phase 2: warps0-3: V = X@Wv (fat) ; warps4-7: scores + softmax -> P ----
    if (grp == 0) {
        FC acc[2][4];
#pragma unroll
        for (int i = 0; i < 2; i++)
#pragma unroll
            for (int j = 0; j < 4; j++) wmma::fill_fragment(acc[i][j], 0.0f);
#pragma unroll
        for (int k = 0; k < 128; k += 16) {
            FA ah[2], al[2];
            FBc bh[4], bl[4];
#pragma unroll
            for (int i = 0; i < 2; i++) {
                wmma::load_matrix_sync(ah[i], xhi + (fm0 + 16 * i) * SB + k, SB);
                wmma::load_matrix_sync(al[i], xlo + (fm0 + 16 * i) * SB + k, SB);
            }
#pragma unroll
            for (int j = 0; j < 4; j++) {
                wmma::load_matrix_sync(bh[j], wa + (fn0 + 16 * j) * SB + k, SB);
                wmma::load_matrix_sync(bl[j], wb + (fn0 + 16 * j) * SB + k, SB);
            }
#pragma unroll
            for (int i = 0; i < 2; i++)
#pragma unroll
                for (int j = 0; j < 4; j++) {
                    wmma::mma_sync(acc[i][j], ah[i], bh[j], acc[i][j]);
                    wmma::mma_sync(acc[i][j], ah[i], bl[j], acc[i][j]);
                    wmma::mma_sync(acc[i][j], al[i], bh[j], acc[i][j]);
                }
        }
        BAR(1);                          // all warps0-3 done reading Wv
        stageW_h(WA, g_Whi[2]);          // stage Wr hi/lo (group-local)
        stageW_h(WB, g_Wlo[2]);
#pragma unroll
        for (int i = 0; i < 2; i++)
#pragma unroll
            for (int j = 0; j < 4; j++)
                wmma::store_matrix_sync(tmpp + (fm0 + 16 * i) * SF + (fn0 + 16 * j),
                                        acc[i][j], SF, wmma::mem_row_major);
        BAR(1);
        // convert V (128 threads: 64 values each)
        const int r = ltid >> 1, c0v = (ltid & 1) * 64;
#pragma unroll
        for (int jj = 0; jj < 16; jj++) {
            float4 f = *(const float4*)(tmpp + r * SF + c0v + jj * 4);
            unsigned h0, l0, h1, l1;
            split2(f.x, f.y, h0, l0);
            split2(f.z, f.w, h1, l1);
            *(uint2*)(sm + VHI + (r * SB + c0v + jj * 4) * 2) = make_uint2(h0, h1);
            *(uint2*)(sm + VLO + (r * SB + c0v + jj * 4) * 2) = make_uint2(l0, l1);
        }
    } else {
        // scores: warp owns rows 16*w4..+15, ALL 64 cols (1m x 4n)
        const int sm0 = 16 * w4;
        const __nv_bfloat16* thi = (const __nv_bfloat16*)(sm + THI);
        const __nv_bfloat16* tlo = (const __nv_bfloat16*)(sm + TLO);
        FC acc[4];
#pragma unroll
        for (int j = 0; j < 4; j++) wmma::fill_fragment(acc[j], 0.0f);
#pragma unroll
        for (int k = 0; k < 128; k += 16) {
            FA th, tl;
            FBc xh[4], xl[4];
            wmma::load_matrix_sync(th, thi + sm0 * SB + k, SB);
            wmma::load_matrix_sync(tl, tlo + sm0 * SB + k, SB);
#pragma unroll
            for (int j = 0; j < 4; j++) {
                wmma::load_matrix_sync(xh[j], xhi + (16 * j) * SB + k, SB);
                wmma::load_matrix_sync(xl[j], xlo + (16 * j) * SB + k, SB);
            }
#pragma unroll
            for (int j = 0; j < 4; j++) {
                wmma::mma_sync(acc[j], th, xh[j], acc[j]);
                wmma::mma_sync(acc[j], th, xl[j], acc[j]);
                wmma::mma_sync(acc[j], tl, xh[j], acc[j]);
            }
        }
        float* scp = (float*)(sm + SC);
#pragma unroll
        for (int j = 0; j < 4; j++)
            wmma::store_matrix_sync(scp + sm0 * SS + 16 * j, acc[j], SS,
                                    wmma::mem_row_major);
        __syncwarp();
        // softmax: this warp's 16 rows; lane pairs split 64 cols
        const int ln = tid & 31;
        const int r = sm0 + (ln >> 1), c0v = (ln & 1) * 32;
        float s[32];
#pragma unroll
        for (int j = 0; j < 32; j += 4) {
            float4 f = *(const float4*)(scp + r * SS + c0v + j);
            s[j] = f.x; s[j + 1] = f.y; s[j + 2] = f.z; s[j + 3] = f.w;
        }
        float mx = s[0];
#pragma unroll
        for (int j = 1; j < 32; j++) mx = fmaxf(mx, s[j]);
        mx = fmaxf(mx, __shfl_xor_sync(0xffffffffu, mx, 1));
        float sum = 0.f;
#pragma unroll
        for (int j = 0; j < 32; j++) { s[j] = __expf(s[j] - mx); sum += s[j]; }
        sum += __shfl_xor_sync(0xffffffffu, sum, 1);
        const float inv = 1.0f / sum;
#pragma unroll
        for (int j = 0; j < 32; j += 2) {
            unsigned h, l;
            split2(s[j] * inv, s[j + 1] * inv, h, l);
            *(unsigned*)(sm + THI + (r * SP + c0v + j) * 2) = h;
            *(unsigned*)(sm + TLO + (r * SP + c0v + j) * 2) = l;
        }
    }
    __syncthreads();   // V converted, P written, TMP free

    // ---- phase 3: warps0-3: X@Wr (fat, keep in regs) ; warps4-7: P@V -> TMP ----
    FC acc[2][4];
#pragma unroll
    for (int i = 0; i < 2; i++)
#pragma unroll
        for (int j = 0; j < 4; j++) wmma::fill_fragment(acc[i][j], 0.0f);

    if (grp == 0) {
        CPA_WAIT();                       // Wr hi/lo landed (issued by this group)
#pragma unroll
        for (int k = 0; k < 128; k += 16) {
            FA ah[2], al[2];
            FBc wh[4], wl[4];
#pragma unroll
            for (int i = 0; i < 2; i++) {
                wmma::load_matrix_sync(ah[i], xhi + (fm0 + 16 * i) * SB + k, SB);
                wmma::load_matrix_sync(al[i], xlo + (fm0 + 16 * i) * SB + k, SB);
            }
#pragma unroll
            for (int j = 0; j < 4; j++) {
                wmma::load_matrix_sync(wh[j], wa + (fn0 + 16 * j) * SB + k, SB);
                wmma::load_matrix_sync(wl[j], wb + (fn0 + 16 * j) * SB + k, SB);
            }
#pragma unroll
            for (int i = 0; i < 2; i++)
#pragma unroll
                for (int j = 0; j < 4; j++) {
                    wmma::mma_sync(acc[i][j], ah[i], wh[j], acc[i][j]);
                    wmma::mma_sync(acc[i][j], ah[i], wl[j], acc[i][j]);
                    wmma::mma_sync(acc[i][j], al[i], wh[j], acc[i][j]);
                }
        }
    } else {
        const __nv_bfloat16* phi = (const __nv_bfloat16*)(sm + THI);
        const __nv_bfloat16* plo = (const __nv_bfloat16*)(sm + TLO);
        const __nv_bfloat16* vhi = (const __nv_bfloat16*)(sm + VHI);
        const __nv_bfloat16* vlo = (const __nv_bfloat16*)(sm + VLO);
#pragma unroll
        for (int k = 0; k < 64; k += 16) {
            FA ph[2], pl[2];
            FBr vh[4], vl[4];
#pragma unroll
            for (int i = 0; i < 2; i++) {
                wmma::load_matrix_sync(ph[i], phi + (fm0 + 16 * i) * SP + k, SP);
                wmma::load_matrix_sync(pl[i], plo + (fm0 + 16 * i) * SP + k, SP);
            }
#pragma unroll
            for (int j = 0; j < 4; j++) {
                wmma::load_matrix_sync(vh[j], vhi + k * SB + fn0 + 16 * j, SB);
                wmma::load_matrix_sync(vl[j], vlo + k * SB + fn0 + 16 * j, SB);
            }
#pragma unroll
            for (int i = 0; i < 2; i++)
#pragma unroll
                for (int j = 0; j < 4; j++) {
                    wmma::mma_sync(acc[i][j], ph[i], vh[j], acc[i][j]);
                    wmma::mma_sync(acc[i][j], ph[i], vl[j], acc[i][j]);
                    wmma::mma_sync(acc[i][j], pl[i], vh[j], acc[i][j]);
                }
        }
#pragma unroll
        for (int i = 0; i < 2; i++)
#pragma unroll
            for (int j = 0; j < 4; j++)
                wmma::store_matrix_sync(tmpp + (fm0 + 16 * i) * SF + (fn0 + 16 * j),
                                        acc[i][j], SF, wmma::mem_row_major);
    }
    __syncthreads();

    // ---- merge: warps0-3 add P@V partial, relu, store ----
    if (grp == 0) {
        float* outp = out + (size_t)b * 8192;
#pragma unroll
        for (int i = 0; i < 2; i++)
#pragma unroll
            for (int j = 0; j < 4; j++) {
                FC t;
                wmma::load_matrix_sync(t, tmpp + (fm0 + 16 * i) * SF + (fn0 + 16 * j),
                                       SF, wmma::mem_row_major);
#pragma unroll
                for (int e = 0; e < t.num_elements; e++)
                    acc[i][j].x[e] = fmaxf(acc[i][j].x[e] + t.x[e], 0.0f);
                wmma::store_matrix_sync(outp + (fm0 + 16 * i) * 128 + (fn0 + 16 * j),
                                        acc[i][j], 128, wmma::mem_row_major);
            }
    }
}

extern "C" void kernel_launch(void* const* d_in, const int* in_sizes, int n_in,
                              void* d_out, int out_size) {
    const float* x  = (const float*)d_in[0];
    const float* Wq = (const float*)d_in[1];
    const float* Wk = (const float*)d_in[2];
    const float* Wv = (const float*)d_in[3];
    const float* Wr = (const float*)d_in[4];
    float* out = (float*)d_out;

    prep_all<<<256, 256>>>(Wq, Wk, Wv, Wr);
    cudaFuncSetAttribute(autoint_hmma,
                         cudaFuncAttributeMaxDynamicSharedMemorySize, SMEM_BYTES);
    autoint_hmma<<<8192, NT, SMEM_BYTES>>>(x, out);
}